// round 17
// baseline (speedup 1.0000x reference)
#include <cuda_runtime.h>
#include <cuda_fp16.h>
#include <cstdint>

#define B_TOK 8192
#define C_DIM 1024
#define E_NUM 8
#define K_TOP 4
#define H_DIM 4096

// ---------------- scratch (device globals; no allocations allowed) ----------------
__device__ int    g_count[E_NUM];
__device__ int    g_tok[E_NUM * B_TOK];
__device__ int    g_te[B_TOK * K_TOP];
__device__ int    g_tp[B_TOK * K_TOP];
__device__ float  g_tw[B_TOK * K_TOP];
__device__ __half g_h[(size_t)E_NUM * B_TOK * H_DIM];    // hidden acts, half (512 MiB)
__device__ float  g_y[(size_t)E_NUM * B_TOK * C_DIM];    // expert outputs pre-LN (fp32)
__device__ __half g_xc [(size_t)B_TOK * C_DIM];          // x as half [b][C]
__device__ __half g_w1h[(size_t)E_NUM * C_DIM * H_DIM];  // W1 as half [e][K=C][N=H]
__device__ __half g_w2h[(size_t)E_NUM * H_DIM * C_DIM];  // W2 as half [e][K=H][N=C]

// ---------------- helpers ----------------
__device__ __forceinline__ void mma_f16(float (&d)[4], const uint32_t (&a)[4], const uint32_t (&b)[2]) {
    asm volatile(
        "mma.sync.aligned.m16n8k16.row.col.f32.f16.f16.f32 "
        "{%0,%1,%2,%3}, {%4,%5,%6,%7}, {%8,%9}, {%0,%1,%2,%3};\n"
        : "+f"(d[0]), "+f"(d[1]), "+f"(d[2]), "+f"(d[3])
        : "r"(a[0]), "r"(a[1]), "r"(a[2]), "r"(a[3]), "r"(b[0]), "r"(b[1]));
}

#define LDSM_X4(r, addr) \
    asm volatile("ldmatrix.sync.aligned.m8n8.x4.shared.b16 {%0,%1,%2,%3}, [%4];" \
                 : "=r"((r)[0]), "=r"((r)[1]), "=r"((r)[2]), "=r"((r)[3]) : "r"(addr))

#define LDSM_X4_T(r, addr) \
    asm volatile("ldmatrix.sync.aligned.m8n8.x4.trans.shared.b16 {%0,%1,%2,%3}, [%4];" \
                 : "=r"((r)[0]), "=r"((r)[1]), "=r"((r)[2]), "=r"((r)[3]) : "r"(addr))

__device__ __forceinline__ void cp16(uint32_t dst, const void* src, int sz) {
    asm volatile("cp.async.cg.shared.global [%0], [%1], 16, %2;"
                 :: "r"(dst), "l"(src), "r"(sz));
}

__device__ __forceinline__ float quick_gelu(float v) {
    return v / (1.f + __expf(-1.702f * v));
}

// ---------------- kernel 0: both weight converts + counter zeroing, one launch ----------------
__global__ void convert_weights(const float* __restrict__ W1, const float* __restrict__ W2) {
    if (blockIdx.x == 0 && threadIdx.x < E_NUM) g_count[threadIdx.x] = 0;
    constexpr int n4 = (E_NUM * C_DIM * H_DIM) / 4;   // float4 count per weight tensor
    uint2* d1 = (uint2*)g_w1h;
    uint2* d2 = (uint2*)g_w2h;
    int i = blockIdx.x * blockDim.x + threadIdx.x;
    const int stride = gridDim.x * blockDim.x;
    for (; i < 2 * n4; i += stride) {
        const float4* s;
        uint2* d;
        int idx;
        if (i < n4) { s = (const float4*)W1; d = d1; idx = i; }
        else        { s = (const float4*)W2; d = d2; idx = i - n4; }
        float4 v = s[idx];
        __half2 h01 = __floats2half2_rn(v.x, v.y);
        __half2 h23 = __floats2half2_rn(v.z, v.w);
        uint2 o;
        o.x = *reinterpret_cast<uint32_t*>(&h01);
        o.y = *reinterpret_cast<uint32_t*>(&h23);
        d[idx] = o;
    }
}

// ---------------- kernel 1: gating (fp32, numerics unchanged) + x->half ----------------
__global__ void gate_kernel(const float* __restrict__ x,
                            const float* __restrict__ Wg,
                            const float* __restrict__ bg) {
    const int warp = threadIdx.x >> 5;
    const int lane = threadIdx.x & 31;
    const int b = blockIdx.x * 8 + warp;

    float acc[E_NUM];
#pragma unroll
    for (int e = 0; e < E_NUM; e++) acc[e] = 0.f;

    const float* xr = x + (size_t)b * C_DIM;
    __half* xh = (__half*)g_xc + (size_t)b * C_DIM;
    for (int c = lane; c < C_DIM; c += 32) {
        float xv = xr[c];
        xh[c] = __float2half(xv);                  // fused conversion (write-only side effect)
        const float* wr = Wg + c * E_NUM;
#pragma unroll
        for (int e = 0; e < E_NUM; e++) acc[e] += xv * wr[e];
    }
#pragma unroll
    for (int e = 0; e < E_NUM; e++)
#pragma unroll
        for (int o = 16; o > 0; o >>= 1)
            acc[e] += __shfl_xor_sync(0xffffffffu, acc[e], o);

    if (lane == 0) {
        float s[E_NUM];
        float mx = -1e30f;
#pragma unroll
        for (int e = 0; e < E_NUM; e++) { s[e] = acc[e] + bg[e]; mx = fmaxf(mx, s[e]); }
        float sum = 0.f;
#pragma unroll
        for (int e = 0; e < E_NUM; e++) { s[e] = __expf(s[e] - mx); sum += s[e]; }
        float inv = 1.f / sum;
#pragma unroll
        for (int e = 0; e < E_NUM; e++) s[e] *= inv;

#pragma unroll
        for (int k = 0; k < K_TOP; k++) {
            int be = 0; float bv = -1.f;
#pragma unroll
            for (int e = 0; e < E_NUM; e++)
                if (s[e] > bv) { bv = s[e]; be = e; }
            s[be] = -2.f;
            int pos = atomicAdd(&g_count[be], 1);
            g_tok[be * B_TOK + pos] = b;
            g_te[b * K_TOP + k] = be;
            g_tp[b * K_TOP + k] = pos;
            g_tw[b * K_TOP + k] = bv;
        }
    }
}

// ---------------- kernels 2 & 3: fp16 cp.async-pipelined grouped GEMM ----------------
// CTA tile 128(M) x 128(N), 128 threads = 4 warps (2m x 2n), warp tile 64x64. 2 CTAs/SM.
// Bigger warp tile: 128 B of LDSM traffic per MMA (was 192) -> tensor duty up.
// A smem [m][k] (72-half rows), fragments via LDSM.x4.
// B smem [k][n] (136-half rows) staged straight from W [K][N]; fragments via LDSM.x4.trans.
// MODE 1: A = gathered g_xc rows, B = g_w1h, out g_h (half).  K=1024 N=4096
// MODE 2: A = g_h rows,           B = g_w2h, out g_y (fp32).  K=4096 N=1024
template <int K, int N, int MODE>
__global__ __launch_bounds__(128, 2)
void ffn_gemm(const float* __restrict__ bias)   // [E, N]
{
    constexpr int BM = 128, BN = 128, BK = 64, STAGES = 3;
    constexpr int ASTR = 72;                          // halfs per A smem row (144 B)
    constexpr int BSTR = 136;                         // halfs per B smem row (272 B)
    constexpr int A_BYTES = BM * ASTR * 2;            // 18432
    constexpr int B_BYTES = BK * BSTR * 2;            // 17408
    constexpr int STAGE_BYTES = A_BYTES + B_BYTES;    // 35840
    constexpr int KT = K / BK;

    extern __shared__ char sm[];
    __shared__ int rIdx[BM];

    const int e = blockIdx.z;
    const int cnt = g_count[e];
    const int m0 = blockIdx.y * BM;
    if (m0 >= cnt) return;
    const int n0 = blockIdx.x * BN;
    const int tid = threadIdx.x;

    {
        int r = m0 + tid;
        rIdx[tid] = (r < cnt) ? ((MODE == 1) ? g_tok[e * B_TOK + r] : (e * B_TOK + r)) : -1;
    }
    __syncthreads();

    const __half* Abase = (MODE == 1) ? (const __half*)g_xc : (const __half*)g_h;
    const __half* Wh = ((MODE == 1) ? (const __half*)g_w1h : (const __half*)g_w2h)
                       + (size_t)e * (size_t)K * N;   // [K][N]

    // ---- staging plan per stage: A 8 + B 8 chunks of 16B per thread (128 threads) ----
    const uint32_t saddr = (uint32_t)__cvta_generic_to_shared(sm);
    const __half* srcA[8];
    uint32_t dstA[8];
    int szA[8];
#pragma unroll
    for (int u = 0; u < 8; u++) {
        int idx = tid + u * 128;                   // 0..1023
        int row = idx >> 3, c8 = (idx & 7) * 8;    // 8 chunks of 8 halfs per row
        dstA[u] = saddr + (uint32_t)(row * ASTR + c8) * 2u;
        int gr = rIdx[row];
        srcA[u] = Abase + (size_t)(gr < 0 ? 0 : gr) * K + c8;
        szA[u] = (gr < 0) ? 0 : 16;
    }
    const __half* srcB[8];                         // B tile: 64 k-rows x 128 halfs
    uint32_t dstB[8];
#pragma unroll
    for (int u = 0; u < 8; u++) {
        int idx = tid + u * 128;                   // 0..1023
        int r = idx >> 4, c16 = idx & 15;          // 16 chunks of 8 halfs per k-row
        dstB[u] = saddr + (uint32_t)A_BYTES + (uint32_t)(r * BSTR + c16 * 8) * 2u;
        srcB[u] = Wh + (size_t)r * N + n0 + c16 * 8;
    }

#define LOAD_TILE(slot, k0)                                                          \
    do {                                                                             \
        uint32_t so = (uint32_t)(slot) * STAGE_BYTES;                                \
        _Pragma("unroll")                                                            \
        for (int u = 0; u < 8; u++) cp16(dstA[u] + so, srcA[u] + (k0), szA[u]);      \
        _Pragma("unroll")                                                            \
        for (int u = 0; u < 8; u++)                                                  \
            cp16(dstB[u] + so, srcB[u] + (size_t)(k0) * N, 16);                      \
    } while (0)

#pragma unroll
    for (int s = 0; s < STAGES - 1; s++) {
        LOAD_TILE(s, s * BK);
        asm volatile("cp.async.commit_group;");
    }

    const int warp = tid >> 5, lane = tid & 31;
    const int mB = (warp >> 1) * 64;          // 2 m-warps
    const int nB = (warp & 1) * 64;           // 2 n-warps
    const int gr = lane >> 2, gc = lane & 3;

    // A ldmatrix x4: lane l -> row mB + (l&15), k-half (l>>4)*8
    const uint32_t aOff = (uint32_t)((mB + (lane & 15)) * ASTR + (lane >> 4) * 8) * 2u;
    // B ldmatrix x4 trans: group j = lane>>3: k_local = (j&1)*8 + (lane&7), n_local = (j>>1)*8
    const int bj = lane >> 3, brin = lane & 7;
    const uint32_t bOff = (uint32_t)A_BYTES +
        (uint32_t)((((bj & 1) << 3) + brin) * BSTR + nB + ((bj >> 1) << 3)) * 2u;

    float acc[4][8][4];
#pragma unroll
    for (int i = 0; i < 4; i++)
#pragma unroll
        for (int j = 0; j < 8; j++)
#pragma unroll
            for (int l = 0; l < 4; l++) acc[i][j][l] = 0.f;

    int slot = 0;
    for (int kt = 0; kt < KT; kt++) {
        asm volatile("cp.async.wait_group %0;" :: "n"(STAGES - 2));
        __syncthreads();

        int kload = kt + STAGES - 1;
        if (kload < KT) {
            int ls = kload - STAGES * (kload / STAGES);
            LOAD_TILE(ls, kload * BK);
        }
        asm volatile("cp.async.commit_group;");

        const uint32_t stageA = saddr + (uint32_t)slot * STAGE_BYTES + aOff;
        const uint32_t stageB = saddr + (uint32_t)slot * STAGE_BYTES + bOff;
        slot = (slot == STAGES - 1) ? 0 : slot + 1;

#pragma unroll
        for (int kk = 0; kk < 4; kk++) {
            uint32_t af[4][4], bf[8][2];
#pragma unroll
            for (int mi = 0; mi < 4; mi++)
                LDSM_X4(af[mi], stageA + (uint32_t)(mi * 16 * ASTR) * 2u + (uint32_t)kk * 32u);
            // four x4.trans loads cover the warp's 64 n-columns (16 each)
#pragma unroll
            for (int np = 0; np < 4; np++) {
                uint32_t t[4];
                LDSM_X4_T(t, stageB + (uint32_t)(kk * 16 * BSTR) * 2u + (uint32_t)np * 32u);
                bf[2 * np + 0][0] = t[0];
                bf[2 * np + 0][1] = t[1];
                bf[2 * np + 1][0] = t[2];
                bf[2 * np + 1][1] = t[3];
            }
#pragma unroll
            for (int mi = 0; mi < 4; mi++)
#pragma unroll
                for (int ni = 0; ni < 8; ni++)
                    mma_f16(acc[mi][ni], af[mi], bf[ni]);
        }
    }
#undef LOAD_TILE

    // ---- epilogue: +bias, quickGELU, store ----
    const float* bp = bias + (size_t)e * N;
#pragma unroll
    for (int mi = 0; mi < 4; mi++) {
#pragma unroll
        for (int half = 0; half < 2; half++) {
            int lr = mB + mi * 16 + gr + half * 8;
            int grow = m0 + lr;
            if (grow < cnt) {
#pragma unroll
                for (int ni = 0; ni < 8; ni++) {
                    int col = n0 + nB + ni * 8 + gc * 2;
                    float v0 = quick_gelu(acc[mi][ni][half * 2 + 0] + bp[col]);
                    float v1 = quick_gelu(acc[mi][ni][half * 2 + 1] + bp[col + 1]);
                    if (MODE == 1) {
                        __half2 hv = __floats2half2_rn(v0, v1);
                        __half* orow = (__half*)g_h + ((size_t)e * B_TOK + grow) * N;
                        *reinterpret_cast<__half2*>(orow + col) = hv;
                    } else {
                        float* orow = (float*)g_y + ((size_t)e * B_TOK + grow) * N;
                        *reinterpret_cast<float2*>(orow + col) = make_float2(v0, v1);
                    }
                }
            }
        }
    }
}

// ---------------- kernel 4: parallel per-token LayerNorm + weighted combine ----------------
// 8 warps: 2 warps per expert-k; all 4 rows stream concurrently; 2 block barriers total.
__global__ void combine_kernel(const float* __restrict__ ln_g,
                               const float* __restrict__ ln_b,
                               float* __restrict__ out) {
    const int b = blockIdx.x;
    const int tid = threadIdx.x;
    const int lane = tid & 31, warp = tid >> 5;
    const int kk = warp >> 1, hf = warp & 1;      // expert slot, row half

    __shared__ float con[K_TOP][C_DIM];           // per-k contributions (16 KB)
    __shared__ float red[K_TOP][2][2];            // [k][half][{sum, sumsq}]

    const int e   = g_te[b * K_TOP + kk];
    const int pos = g_tp[b * K_TOP + kk];
    const float w = g_tw[b * K_TOP + kk];
    const float* row = g_y + ((size_t)e * B_TOK + pos) * C_DIM;
    const int base = hf * 512;

    float v[16], s = 0.f, s2 = 0.f;
#pragma unroll
    for (int j = 0; j < 16; j++) {
        v[j] = row[base + lane + j * 32];
        s += v[j];
        s2 += v[j] * v[j];
    }
#pragma unroll
    for (int o = 16; o > 0; o >>= 1) {
        s  += __shfl_xor_sync(0xffffffffu, s, o);
        s2 += __shfl_xor_sync(0xffffffffu, s2, o);
    }
    if (lane == 0) { red[kk][hf][0] = s; red[kk][hf][1] = s2; }
    __syncthreads();

    const float S  = red[kk][0][0] + red[kk][1][0];
    const float S2 = red[kk][0][1] + red[kk][1][1];
    const float mean = S * (1.f / C_DIM);
    const float var  = S2 * (1.f / C_DIM) - mean * mean;
    const float rs = rsqrtf(var + 1e-6f);
    const float* gp  = ln_g + e * C_DIM;
    const float* bp2 = ln_b + e * C_DIM;
#pragma unroll
    for (int j = 0; j < 16; j++) {
        int c = base + lane + j * 32;
        con[kk][c] = w * ((v[j] - mean) * rs * gp[c] + bp2[c]);
    }
    __syncthreads();

#pragma unroll
    for (int j = 0; j < 4; j++) {
        int c = tid + j * 256;
        out[(size_t)b * C_DIM + c] = con[0][c] + con[1][c] + con[2][c] + con[3][c];
    }
}

// ---------------- launch ----------------
extern "C" void kernel_launch(void* const* d_in, const int* in_sizes, int n_in,
                              void* d_out, int out_size) {
    const float* x   = (const float*)d_in[0];
    const float* W1  = (const float*)d_in[1];
    const float* b1  = (const float*)d_in[2];
    const float* W2  = (const float*)d_in[3];
    const float* b2  = (const float*)d_in[4];
    const float* lng = (const float*)d_in[5];
    const float* lnb = (const float*)d_in[6];
    const float* Wg  = (const float*)d_in[7];
    const float* bg  = (const float*)d_in[8];
    float* out = (float*)d_out;

    constexpr int SMEM_BYTES = 3 * (128 * 72 * 2 + 64 * 136 * 2);   // 107520

    cudaFuncSetAttribute(ffn_gemm<C_DIM, H_DIM, 1>,
                         cudaFuncAttributeMaxDynamicSharedMemorySize, SMEM_BYTES);
    cudaFuncSetAttribute(ffn_gemm<H_DIM, C_DIM, 2>,
                         cudaFuncAttributeMaxDynamicSharedMemorySize, SMEM_BYTES);

    convert_weights<<<4096, 256>>>(W1, W2);      // also zeroes g_count (block 0)
    gate_kernel<<<B_TOK / 8, 256>>>(x, Wg, bg);  // also emits g_xc (half)
    ffn_gemm<C_DIM, H_DIM, 1><<<dim3(H_DIM / 128, B_TOK / 128, E_NUM), 128, SMEM_BYTES>>>(b1);
    ffn_gemm<H_DIM, C_DIM, 2><<<dim3(C_DIM / 128, B_TOK / 128, E_NUM), 128, SMEM_BYTES>>>(b2);
    combine_kernel<<<B_TOK, 256>>>(lng, lnb, out);
}